// round 13
// baseline (speedup 1.0000x reference)
#include <cuda_runtime.h>

typedef unsigned long long u64;

#define Xd   256
#define Bd   64
#define Td   2048
#define Cc   32      // chunk length (M^32 via 5 squarings)
#define NCc  64      // number of chunks = Td/Cc
#define YHd  64
#define ZHd  16

// ---------------- device scratch (no runtime allocation allowed) ----------------
__device__ __align__(16) float g_drive[Td*Bd*Xd];   // d_t = drive_t + A_b, [t][b][x]
__device__ __align__(16) float g_Xst [Td*Bd*Xd];    // pre-update states x_t, [t][b][x]
__device__ __align__(16) float g_M   [Xd*Xd];       // M = A_w^T (row-major [j][i])
__device__ __align__(16) float g_P0  [Xd*Xd];
__device__ __align__(16) float g_P1  [Xd*Xd];
__device__ __align__(16) float g_E   [NCc*Bd*Xd];   // chunk end states (zero-init scan)
__device__ __align__(16) float g_X0  [NCc*Bd*Xd];   // true chunk initial states
__device__ __align__(16) float g_Cy1T[Xd*Xd];       // Cy1_w^T  [j][o]
__device__ __align__(16) float g_Cz1T[Xd*Xd];
__device__ __align__(16) float g_Cy2T[Xd*YHd];      // Cy2_w^T  [j][o]
__device__ __align__(16) float g_Cz2T[Xd*ZHd];
__device__ __align__(16) float g_WinT[96*Xd];       // concat(K_w, Bm_w)^T  [j][x]
__device__ __align__(16) float g_bias[Xd];          // K_b + Bm_b + A_b

// ---------------- packed f32x2 helpers ----------------
__device__ __forceinline__ void fma2(u64& d, u64 a, u64 b) {
    asm("fma.rn.f32x2 %0, %1, %2, %0;" : "+l"(d) : "l"(a), "l"(b));
}
__device__ __forceinline__ u64 bcast2(float v) {
    u64 r; asm("mov.b64 %0, {%1, %1};" : "=l"(r) : "f"(v)); return r;
}
__device__ __forceinline__ float2 unpack2(u64 v) {
    float2 f; asm("mov.b64 {%0, %1}, %2;" : "=f"(f.x), "=f"(f.y) : "l"(v)); return f;
}
__device__ __forceinline__ float sigm(float v) { return 1.f / (1.f + __expf(-v)); }
__device__ __forceinline__ float fget(float4 v, int q) {
    return q == 0 ? v.x : (q == 1 ? v.y : (q == 2 ? v.z : v.w));
}
// dup-pair store: from packed {lo,hi} produce ulonglong2 {dup(lo),dup(hi)}
__device__ __forceinline__ ulonglong2 dup2(u64 a) {
    float2 p = unpack2(a);
    ulonglong2 o; o.x = bcast2(p.x); o.y = bcast2(p.y); return o;
}

// ---------------- setup: transpose weights into GEMM-friendly layouts ----------------
__global__ __launch_bounds__(256) void setup_kernel(
    const float* __restrict__ A_w,  const float* __restrict__ A_b,
    const float* __restrict__ K_w,  const float* __restrict__ K_b,
    const float* __restrict__ Bm_w, const float* __restrict__ Bm_b,
    const float* __restrict__ Cy1_w, const float* __restrict__ Cz1_w,
    const float* __restrict__ Cy2_w, const float* __restrict__ Cz2_w)
{
    int n = blockIdx.x * 256 + threadIdx.x;
    int stride = gridDim.x * 256;
    for (int i = n; i < Xd*Xd; i += stride) {
        int j = i >> 8, k = i & 255;
        g_M[i]    = A_w  [k*Xd + j];
        g_Cy1T[i] = Cy1_w[k*Xd + j];
        g_Cz1T[i] = Cz1_w[k*Xd + j];
    }
    for (int i = n; i < Xd*YHd; i += stride) { int j = i >> 6, o = i & 63; g_Cy2T[i] = Cy2_w[o*Xd + j]; }
    for (int i = n; i < Xd*ZHd; i += stride) { int j = i >> 4, o = i & 15; g_Cz2T[i] = Cz2_w[o*Xd + j]; }
    for (int i = n; i < 96*Xd;  i += stride) {
        int j = i >> 8, x = i & 255;
        g_WinT[i] = (j < 64) ? K_w[x*64 + j] : Bm_w[x*32 + (j - 64)];
    }
    for (int i = n; i < Xd; i += stride) g_bias[i] = K_b[i] + Bm_b[i] + A_b[i];
}

// ---------------- drive: d[t][b][x] = y_t·K^T + u_t·Bm^T + (K_b+Bm_b+A_b) ----------------
__global__ __launch_bounds__(256) void drive_kernel(
    const float* __restrict__ y, const float* __restrict__ u)
{
    __shared__ __align__(16) float sIn[64*96];
    int t = blockIdx.x, tid = threadIdx.x;
    for (int m = tid; m < 64*64; m += 256) { int b = m >> 6, c = m & 63; sIn[b*96 + c]      = y[(b*Td + t)*64 + c]; }
    for (int m = tid; m < 64*32; m += 256) { int b = m >> 5, c = m & 31; sIn[b*96 + 64 + c] = u[(b*Td + t)*32 + c]; }
    __syncthreads();
    int tr = tid >> 5, tc = tid & 31;
    u64 acc[8][4];
    ulonglong2 b01 = *(const ulonglong2*)&g_bias[tc*8];
    ulonglong2 b23 = *(const ulonglong2*)&g_bias[tc*8 + 4];
    #pragma unroll
    for (int r = 0; r < 8; r++) { acc[r][0]=b01.x; acc[r][1]=b01.y; acc[r][2]=b23.x; acc[r][3]=b23.y; }
    #pragma unroll 4
    for (int j = 0; j < 96; j++) {
        ulonglong2 w01 = *(const ulonglong2*)&g_WinT[j*Xd + tc*8];
        ulonglong2 w23 = *(const ulonglong2*)&g_WinT[j*Xd + tc*8 + 4];
        #pragma unroll
        for (int r = 0; r < 8; r++) {
            u64 vv = bcast2(sIn[(tr*8 + r)*96 + j]);
            fma2(acc[r][0], vv, w01.x); fma2(acc[r][1], vv, w01.y);
            fma2(acc[r][2], vv, w23.x); fma2(acc[r][3], vv, w23.y);
        }
    }
    float* dp = &g_drive[t*Bd*Xd];
    #pragma unroll
    for (int r = 0; r < 8; r++) {
        int b = tr*8 + r;
        ulonglong2 o0; o0.x = acc[r][0]; o0.y = acc[r][1];
        ulonglong2 o1; o1.x = acc[r][2]; o1.y = acc[r][3];
        *(ulonglong2*)&dp[b*Xd + tc*8]     = o0;
        *(ulonglong2*)&dp[b*Xd + tc*8 + 4] = o1;
    }
}

// ---------------- matsq: Q = P·P (256x256 row-major) ----------------
__global__ __launch_bounds__(256) void matsq_kernel(
    const float* __restrict__ P, float* __restrict__ Q)
{
    __shared__ __align__(16) float sL[64*68];
    int i0 = (blockIdx.x >> 2) * 64, k0 = (blockIdx.x & 3) * 64;
    int tid = threadIdx.x, tr = tid >> 4, tc = tid & 15;
    u64 acc[4][2];
    #pragma unroll
    for (int r = 0; r < 4; r++) { acc[r][0] = 0ull; acc[r][1] = 0ull; }
    for (int jb = 0; jb < 4; jb++) {
        for (int m = tid; m < 4096; m += 256) {
            int r = m >> 6, c = m & 63;
            sL[r*68 + c] = P[(i0 + r)*Xd + jb*64 + c];
        }
        __syncthreads();
        #pragma unroll 8
        for (int j = 0; j < 64; j++) {
            ulonglong2 w = *(const ulonglong2*)&P[(jb*64 + j)*Xd + k0 + tc*4];
            #pragma unroll
            for (int r = 0; r < 4; r++) {
                u64 vv = bcast2(sL[(tr*4 + r)*68 + j]);
                fma2(acc[r][0], vv, w.x); fma2(acc[r][1], vv, w.y);
            }
        }
        __syncthreads();
    }
    #pragma unroll
    for (int r = 0; r < 4; r++) {
        ulonglong2 o; o.x = acc[r][0]; o.y = acc[r][1];
        *(ulonglong2*)&Q[(i0 + tr*4 + r)*Xd + k0 + tc*4] = o;
    }
}

// ---------------- scan_main v4: balanced 2x4 warp split, dup-state smem ----------
// V <- V·M + D_k. statesOut (if set) receives the PRE-update state.
// Warp w: row-group rw=w>>2 (16 rows), col-group cw=w&3 (64 cols).
// Lane ln: rl=ln>>3 -> 4 rows at rw*16+rl*4; cl=ln&7 -> 8 cols at cw*64+cl*8.
// Weight rows now read by only 2 warps (vs 8) -> 4x less crossbar traffic.
// smem: sV2 64KB + sM 2x32KB = 128KB dynamic.
#define SCAN_SMEM ((32*Xd*2 + 2*32*Xd)*4)

__global__ __launch_bounds__(256) void scan_main(
    const float* __restrict__ M, const float* __restrict__ D,
    const float* __restrict__ init, float* __restrict__ statesOut,
    float* __restrict__ finalOut, int nSteps)
{
    extern __shared__ __align__(16) float sm[];
    u64*   sV2 = (u64*)sm;            // 32*256 u64 (dup pairs)
    float* sM  = sm + 32*Xd*2;        // 2 * 32*256 float
    int chunk = blockIdx.x >> 1;
    int b0 = (blockIdx.x & 1) * 32;
    int tid = threadIdx.x, w = tid >> 5, ln = tid & 31;
    int rowb = (w >> 2) * 16 + (ln >> 3) * 4;   // 4 owned rows
    int colb = (w & 3) * 64 + (ln & 7) * 8;     // 8 owned cols (4 pairs)

    if (init) {
        const float4* ip = (const float4*)(init + ((size_t)chunk*Bd + b0)*Xd);
        #pragma unroll
        for (int i = 0; i < 8; i++) {
            float4 v = ip[tid + i*256];
            ulonglong2* dst = (ulonglong2*)&sV2[(tid + i*256)*4];
            ulonglong2 a; a.x = bcast2(v.x); a.y = bcast2(v.y);
            ulonglong2 b; b.x = bcast2(v.z); b.y = bcast2(v.w);
            dst[0] = a; dst[1] = b;
        }
    } else {
        ulonglong2 z; z.x = 0ull; z.y = 0ull;
        #pragma unroll
        for (int i = 0; i < 8; i++) {
            ulonglong2* dst = (ulonglong2*)&sV2[(tid + i*256)*4];
            dst[0] = z; dst[1] = z;
        }
    }
    {   // stage M tile 0 into buffer 0
        const float4* src = (const float4*)M;
        float4* dst = (float4*)sM;
        #pragma unroll
        for (int i = 0; i < 8; i++) dst[tid + i*256] = src[tid + i*256];
    }
    __syncthreads();
    int buf = 0;

    for (int k = 0; k < nSteps; k++) {
        size_t rowbase = ((size_t)(chunk*nSteps + k)*Bd + b0)*Xd;
        // acc init from D at owned rows/cols
        u64 acc[4][4];
        {
            const float* Dp = D + rowbase;
            #pragma unroll
            for (int r = 0; r < 4; r++) {
                ulonglong2 a0 = *(const ulonglong2*)&Dp[(rowb + r)*Xd + colb];
                ulonglong2 a1 = *(const ulonglong2*)&Dp[(rowb + r)*Xd + colb + 4];
                acc[r][0]=a0.x; acc[r][1]=a0.y; acc[r][2]=a1.x; acc[r][3]=a1.y;
            }
        }
        if (statesOut) {   // extract lows of dup pairs -> contiguous floats
            float2* sp = (float2*)(statesOut + rowbase);
            #pragma unroll
            for (int i = 0; i < 16; i++) {
                ulonglong2 q = ((const ulonglong2*)sV2)[tid + i*256];
                float2 o; o.x = unpack2(q.x).x; o.y = unpack2(q.y).x;
                sp[tid + i*256] = o;
            }
        }
        for (int tt = 0; tt < 8; tt++) {
            int nt = (tt + 1) & 7;
            float4 pf[8];
            {   // prefetch next M tile (cyclic; feeds next iter/step)
                const float4* src = (const float4*)(M + nt*32*Xd);
                #pragma unroll
                for (int i = 0; i < 8; i++) pf[i] = src[tid + i*256];
            }
            const float* mb = sM + buf*(32*Xd);
            #pragma unroll 2
            for (int jj = 0; jj < 32; jj += 4) {
                ulonglong2 va[4], vb[4];   // dup pairs for j..j+3 of 4 owned rows
                #pragma unroll
                for (int r = 0; r < 4; r++) {
                    const ulonglong2* vp = (const ulonglong2*)&sV2[(rowb + r)*Xd + tt*32 + jj];
                    va[r] = vp[0]; vb[r] = vp[1];
                }
                #pragma unroll
                for (int q = 0; q < 4; q++) {
                    ulonglong2 m0 = *(const ulonglong2*)&mb[(jj+q)*Xd + colb];      // 128B/warp
                    ulonglong2 m1 = *(const ulonglong2*)&mb[(jj+q)*Xd + colb + 4];
                    #pragma unroll
                    for (int r = 0; r < 4; r++) {
                        u64 vv = (q == 0) ? va[r].x : (q == 1) ? va[r].y
                               : (q == 2) ? vb[r].x : vb[r].y;
                        fma2(acc[r][0], vv, m0.x); fma2(acc[r][1], vv, m0.y);
                        fma2(acc[r][2], vv, m1.x); fma2(acc[r][3], vv, m1.y);
                    }
                }
            }
            {   // stage prefetched tile into the other buffer
                float4* dst = (float4*)(sM + (buf^1)*(32*Xd));
                #pragma unroll
                for (int i = 0; i < 8; i++) dst[tid + i*256] = pf[i];
            }
            __syncthreads();
            buf ^= 1;
        }
        // write new V (duplicated) at owned rows/cols
        #pragma unroll
        for (int r = 0; r < 4; r++) {
            *(ulonglong2*)&sV2[(rowb + r)*Xd + colb]     = dup2(acc[r][0]);
            *(ulonglong2*)&sV2[(rowb + r)*Xd + colb + 2] = dup2(acc[r][1]);
            *(ulonglong2*)&sV2[(rowb + r)*Xd + colb + 4] = dup2(acc[r][2]);
            *(ulonglong2*)&sV2[(rowb + r)*Xd + colb + 6] = dup2(acc[r][3]);
        }
        __syncthreads();
    }
    if (finalOut) {
        float2* fp = (float2*)(finalOut + ((size_t)chunk*Bd + b0)*Xd);
        #pragma unroll
        for (int i = 0; i < 16; i++) {
            ulonglong2 q = ((const ulonglong2*)sV2)[tid + i*256];
            float2 o; o.x = unpack2(q.x).x; o.y = unpack2(q.y).x;
            fp[tid + i*256] = o;
        }
    }
}

// ---------------- carry scan: 32 CTAs x 2 batch rows ----------------
__global__ __launch_bounds__(128) void scan_carry(
    const float* __restrict__ M, const float* __restrict__ D,
    float* __restrict__ statesOut, int nSteps)
{
    __shared__ __align__(16) float sV[2*Xd];
    int b0 = blockIdx.x * 2;
    int tid = threadIdx.x, tr = tid >> 6, tc = tid & 63;
    {
        float4 z = {0.f,0.f,0.f,0.f};
        for (int i = tid; i < 2*Xd/4; i += 128) ((float4*)sV)[i] = z;
    }
    __syncthreads();
    for (int k = 0; k < nSteps; k++) {
        size_t rowbase = ((size_t)k*Bd + b0)*Xd;
        {
            float4* sp = (float4*)(statesOut + rowbase);
            for (int i = tid; i < 2*Xd/4; i += 128) sp[i] = ((float4*)sV)[i];
        }
        ulonglong2 acc = *(const ulonglong2*)&D[rowbase + tr*Xd + tc*4];
        #pragma unroll 8
        for (int j = 0; j < Xd; j++) {
            ulonglong2 wv = *(const ulonglong2*)&M[j*Xd + tc*4];
            u64 vv = bcast2(sV[tr*Xd + j]);
            fma2(acc.x, vv, wv.x); fma2(acc.y, vv, wv.y);
        }
        __syncthreads();
        *(ulonglong2*)&sV[tr*Xd + tc*4] = acc;
        __syncthreads();
    }
}

// ---------------- heads v4: balanced 2x4 warp split in L1 ----------------
// smem: sX2 64x256 u64 (128KB) + sW 32x256 f (32KB, single buffer) + sH 64x256 f (64KB)
//       = 224KB dynamic (<= 227KB opt-in).
#define HEADS_SMEM ((64*Xd*2 + 32*Xd + 64*Xd)*4)

// sH = relu(X @ W1T + b1); warp w: rw=w>>2 (32 rows), cw=w&3 (64 cols).
// Lane ln: rl=ln>>3 -> 8 rows at rw*32+rl*8; cl=ln&7 -> 8 cols (4 pairs).
__device__ __forceinline__ void mlp_l1(
    const float* __restrict__ W1, const float* __restrict__ b1,
    const u64* sX2, float* sW, float* sH, int tid)
{
    int w = tid >> 5, ln = tid & 31;
    int rowb = (w >> 2) * 32 + (ln >> 3) * 8;   // 8 owned rows
    int colb = (w & 3) * 64 + (ln & 7) * 8;     // 8 owned cols (4 pairs)
    u64 acc[8][4];
    {
        ulonglong2 bb0 = *(const ulonglong2*)&b1[colb];
        ulonglong2 bb1 = *(const ulonglong2*)&b1[colb + 4];
        #pragma unroll
        for (int r = 0; r < 8; r++) { acc[r][0]=bb0.x; acc[r][1]=bb0.y; acc[r][2]=bb1.x; acc[r][3]=bb1.y; }
    }
    {   // stage tile 0
        const float4* src = (const float4*)W1;
        float4* dst = (float4*)sW;
        #pragma unroll
        for (int i = 0; i < 8; i++) dst[tid + i*256] = src[tid + i*256];
    }
    __syncthreads();
    for (int kt = 0; kt < 8; kt++) {
        float4 pf[8];
        if (kt < 7) {
            const float4* src = (const float4*)(W1 + (kt+1)*32*Xd);
            #pragma unroll
            for (int i = 0; i < 8; i++) pf[i] = src[tid + i*256];
        }
        #pragma unroll 2
        for (int jj = 0; jj < 32; jj += 4) {
            ulonglong2 va[8], vb[8];
            #pragma unroll
            for (int r = 0; r < 8; r++) {
                const ulonglong2* vp = (const ulonglong2*)&sX2[(rowb + r)*Xd + kt*32 + jj];
                va[r] = vp[0]; vb[r] = vp[1];
            }
            #pragma unroll
            for (int q = 0; q < 4; q++) {
                ulonglong2 m0 = *(const ulonglong2*)&sW[(jj+q)*Xd + colb];
                ulonglong2 m1 = *(const ulonglong2*)&sW[(jj+q)*Xd + colb + 4];
                #pragma unroll
                for (int r = 0; r < 8; r++) {
                    u64 vv = (q == 0) ? va[r].x : (q == 1) ? va[r].y
                           : (q == 2) ? vb[r].x : vb[r].y;
                    fma2(acc[r][0], vv, m0.x); fma2(acc[r][1], vv, m0.y);
                    fma2(acc[r][2], vv, m1.x); fma2(acc[r][3], vv, m1.y);
                }
            }
        }
        __syncthreads();                 // all reads of sW done
        if (kt < 7) {
            float4* dst = (float4*)sW;
            #pragma unroll
            for (int i = 0; i < 8; i++) dst[tid + i*256] = pf[i];
            __syncthreads();             // new tile visible
        }
    }
    #pragma unroll
    for (int r = 0; r < 8; r++) {
        float2 p0 = unpack2(acc[r][0]), p1 = unpack2(acc[r][1]);
        float2 p2 = unpack2(acc[r][2]), p3 = unpack2(acc[r][3]);
        float4 o0 = {fmaxf(p0.x,0.f), fmaxf(p0.y,0.f), fmaxf(p1.x,0.f), fmaxf(p1.y,0.f)};
        float4 o1 = {fmaxf(p2.x,0.f), fmaxf(p2.y,0.f), fmaxf(p3.x,0.f), fmaxf(p3.y,0.f)};
        *(float4*)&sH[(rowb + r)*Xd + colb]     = o0;
        *(float4*)&sH[(rowb + r)*Xd + colb + 4] = o1;
    }
    __syncthreads();
}

__global__ __launch_bounds__(256) void heads_kernel(
    const float* __restrict__ Cy1_b, const float* __restrict__ Cy2_b,
    const float* __restrict__ Cz1_b, const float* __restrict__ Cz2_b,
    float* __restrict__ outY, float* __restrict__ outZ)
{
    extern __shared__ __align__(16) float sm[];
    u64*   sX2 = (u64*)sm;              // 64*256 u64 (dup)
    float* sW  = sm + 64*Xd*2;          // 32*256
    float* sH  = sm + 64*Xd*2 + 32*Xd;  // 64*256
    int t = blockIdx.x, tid = threadIdx.x;

    {   // load X_t and duplicate into sX2
        const float4* xp = (const float4*)&g_Xst[(size_t)t*Bd*Xd];
        #pragma unroll
        for (int i = 0; i < 16; i++) {
            float4 v = xp[tid + i*256];
            ulonglong2* dst = (ulonglong2*)&sX2[(tid + i*256)*4];
            ulonglong2 a; a.x = bcast2(v.x); a.y = bcast2(v.y);
            ulonglong2 b; b.x = bcast2(v.z); b.y = bcast2(v.w);
            dst[0] = a; dst[1] = b;
        }
    }
    __syncthreads();

    // ===== Y head =====
    mlp_l1(g_Cy1T, Cy1_b, sX2, sW, sH, tid);
    {   // L2-Y: 64x64 = sigm(H @ Cy2T + b2); 8 warps x 8 rows, lane -> col pair
        int tr = tid >> 5, lane = tid & 31;
        u64 acc[8];
        u64 bb = *(const u64*)&Cy2_b[lane*2];
        #pragma unroll
        for (int r = 0; r < 8; r++) acc[r] = bb;
        #pragma unroll 4
        for (int jj = 0; jj < Xd; jj += 4) {
            float4 v[8];
            #pragma unroll
            for (int r = 0; r < 8; r++) v[r] = *(const float4*)&sH[(tr*8 + r)*Xd + jj];
            #pragma unroll
            for (int q = 0; q < 4; q++) {
                u64 wv = *(const u64*)&g_Cy2T[(jj+q)*YHd + lane*2];
                #pragma unroll
                for (int r = 0; r < 8; r++) fma2(acc[r], bcast2(fget(v[r], q)), wv);
            }
        }
        #pragma unroll
        for (int r = 0; r < 8; r++) {
            int b = tr*8 + r;
            float2 p = unpack2(acc[r]);
            float2 o = {sigm(p.x), sigm(p.y)};
            *(float2*)&outY[((size_t)b*Td + t)*YHd + lane*2] = o;
        }
    }
    __syncthreads();

    // ===== Z head =====
    mlp_l1(g_Cz1T, Cz1_b, sX2, sW, sH, tid);
    {   // L2-Z: 64x16; 4 threads per row, 4 cols each
        int row = tid >> 2, cz = (tid & 3) * 4;
        ulonglong2 acc = *(const ulonglong2*)&Cz2_b[cz];
        #pragma unroll 4
        for (int jj = 0; jj < Xd; jj += 4) {
            float4 v = *(const float4*)&sH[row*Xd + jj];
            #pragma unroll
            for (int q = 0; q < 4; q++) {
                ulonglong2 wv = *(const ulonglong2*)&g_Cz2T[(jj+q)*ZHd + cz];
                u64 hv = bcast2(fget(v, q));
                fma2(acc.x, hv, wv.x); fma2(acc.y, hv, wv.y);
            }
        }
        float2 p0 = unpack2(acc.x), p1 = unpack2(acc.y);
        float4 o = {sigm(p0.x), sigm(p0.y), sigm(p1.x), sigm(p1.y)};
        *(float4*)&outZ[((size_t)row*Td + t)*ZHd + cz] = o;
    }
}

// ---------------- launch ----------------
extern "C" void kernel_launch(void* const* d_in, const int* in_sizes, int n_in,
                              void* d_out, int out_size)
{
    (void)in_sizes; (void)n_in; (void)out_size;
    const float* y     = (const float*)d_in[0];
    const float* u     = (const float*)d_in[1];
    const float* A_w   = (const float*)d_in[2];
    const float* A_b   = (const float*)d_in[3];
    const float* K_w   = (const float*)d_in[4];
    const float* K_b   = (const float*)d_in[5];
    const float* Bm_w  = (const float*)d_in[6];
    const float* Bm_b  = (const float*)d_in[7];
    const float* Cy1_w = (const float*)d_in[8];
    const float* Cy1_b = (const float*)d_in[9];
    const float* Cy2_w = (const float*)d_in[10];
    const float* Cy2_b = (const float*)d_in[11];
    const float* Cz1_w = (const float*)d_in[12];
    const float* Cz1_b = (const float*)d_in[13];
    const float* Cz2_w = (const float*)d_in[14];
    const float* Cz2_b = (const float*)d_in[15];
    float* outY = (float*)d_out;
    float* outZ = outY + (size_t)Bd*Td*YHd;

    float *pM, *pP0, *pP1, *pDrive, *pE, *pX0, *pX;
    cudaGetSymbolAddress((void**)&pM,  g_M);
    cudaGetSymbolAddress((void**)&pP0, g_P0);
    cudaGetSymbolAddress((void**)&pP1, g_P1);
    cudaGetSymbolAddress((void**)&pDrive, g_drive);
    cudaGetSymbolAddress((void**)&pE,  g_E);
    cudaGetSymbolAddress((void**)&pX0, g_X0);
    cudaGetSymbolAddress((void**)&pX,  g_Xst);

    cudaFuncSetAttribute(scan_main,   cudaFuncAttributeMaxDynamicSharedMemorySize, SCAN_SMEM);
    cudaFuncSetAttribute(heads_kernel, cudaFuncAttributeMaxDynamicSharedMemorySize, HEADS_SMEM);

    setup_kernel<<<256, 256>>>(A_w, A_b, K_w, K_b, Bm_w, Bm_b, Cy1_w, Cz1_w, Cy2_w, Cz2_w);
    drive_kernel<<<Td, 256>>>(y, u);

    // Mc = M^32 by repeated squaring
    matsq_kernel<<<16, 256>>>(pM,  pP0);   // M^2
    matsq_kernel<<<16, 256>>>(pP0, pP1);   // M^4
    matsq_kernel<<<16, 256>>>(pP1, pP0);   // M^8
    matsq_kernel<<<16, 256>>>(pP0, pP1);   // M^16
    matsq_kernel<<<16, 256>>>(pP1, pP0);   // M^32

    // pass 1: per-chunk zero-start recurrences -> chunk end states E_c
    scan_main<<<NCc*2, 256, SCAN_SMEM>>>(pM, pDrive, nullptr, nullptr, pE, Cc);
    // carry: X0_{c+1} = X0_c * M^32 + E_c  (stores pre-update X0_c)
    scan_carry<<<32, 128>>>(pP0, pE, pX0, NCc);
    // pass 2: re-run each chunk from true X0_c, streaming pre-update states
    scan_main<<<NCc*2, 256, SCAN_SMEM>>>(pM, pDrive, pX0, pX, nullptr, Cc);

    heads_kernel<<<Td, 256, HEADS_SMEM>>>(Cy1_b, Cy2_b, Cz1_b, Cz2_b, outY, outZ);
}

// round 14
// speedup vs baseline: 1.3894x; 1.3894x over previous
#include <cuda_runtime.h>

typedef unsigned long long u64;

#define Xd   256
#define Bd   64
#define Td   2048
#define Cc   32      // chunk length (M^32 via 5 squarings)
#define NCc  64      // number of chunks = Td/Cc
#define YHd  64
#define ZHd  16

// ---------------- device scratch (no runtime allocation allowed) ----------------
__device__ __align__(16) float g_drive[Td*Bd*Xd];   // d_t = drive_t + A_b, [t][b][x]
__device__ __align__(16) float g_Xst [Td*Bd*Xd];    // pre-update states x_t, [t][b][x]
__device__ __align__(16) float g_M   [Xd*Xd];       // M = A_w^T (row-major [j][i])
__device__ __align__(16) float g_P0  [Xd*Xd];
__device__ __align__(16) float g_P1  [Xd*Xd];
__device__ __align__(16) float g_E   [NCc*Bd*Xd];   // chunk end states (zero-init scan)
__device__ __align__(16) float g_X0  [NCc*Bd*Xd];   // true chunk initial states
__device__ __align__(16) float g_Cy1T[Xd*Xd];       // Cy1_w^T  [j][o]
__device__ __align__(16) float g_Cz1T[Xd*Xd];
__device__ __align__(16) float g_Cy2T[Xd*YHd];      // Cy2_w^T  [j][o]
__device__ __align__(16) float g_Cz2T[Xd*ZHd];
__device__ __align__(16) float g_WinT[96*Xd];       // concat(K_w, Bm_w)^T  [j][x]
__device__ __align__(16) float g_bias[Xd];          // K_b + Bm_b + A_b

// ---------------- packed f32x2 helpers ----------------
__device__ __forceinline__ void fma2(u64& d, u64 a, u64 b) {
    asm("fma.rn.f32x2 %0, %1, %2, %0;" : "+l"(d) : "l"(a), "l"(b));
}
__device__ __forceinline__ u64 bcast2(float v) {
    u64 r; asm("mov.b64 %0, {%1, %1};" : "=l"(r) : "f"(v)); return r;
}
__device__ __forceinline__ float2 unpack2(u64 v) {
    float2 f; asm("mov.b64 {%0, %1}, %2;" : "=f"(f.x), "=f"(f.y) : "l"(v)); return f;
}
__device__ __forceinline__ float sigm(float v) { return 1.f / (1.f + __expf(-v)); }
__device__ __forceinline__ float fget(float4 v, int q) {
    return q == 0 ? v.x : (q == 1 ? v.y : (q == 2 ? v.z : v.w));
}
// dup-pair store: from packed {lo,hi} produce ulonglong2 {dup(lo),dup(hi)}
__device__ __forceinline__ ulonglong2 dup2(u64 a) {
    float2 p = unpack2(a);
    ulonglong2 o; o.x = bcast2(p.x); o.y = bcast2(p.y); return o;
}

// ---------------- setup: transpose weights into GEMM-friendly layouts ----------------
__global__ __launch_bounds__(256) void setup_kernel(
    const float* __restrict__ A_w,  const float* __restrict__ A_b,
    const float* __restrict__ K_w,  const float* __restrict__ K_b,
    const float* __restrict__ Bm_w, const float* __restrict__ Bm_b,
    const float* __restrict__ Cy1_w, const float* __restrict__ Cz1_w,
    const float* __restrict__ Cy2_w, const float* __restrict__ Cz2_w)
{
    int n = blockIdx.x * 256 + threadIdx.x;
    int stride = gridDim.x * 256;
    for (int i = n; i < Xd*Xd; i += stride) {
        int j = i >> 8, k = i & 255;
        g_M[i]    = A_w  [k*Xd + j];
        g_Cy1T[i] = Cy1_w[k*Xd + j];
        g_Cz1T[i] = Cz1_w[k*Xd + j];
    }
    for (int i = n; i < Xd*YHd; i += stride) { int j = i >> 6, o = i & 63; g_Cy2T[i] = Cy2_w[o*Xd + j]; }
    for (int i = n; i < Xd*ZHd; i += stride) { int j = i >> 4, o = i & 15; g_Cz2T[i] = Cz2_w[o*Xd + j]; }
    for (int i = n; i < 96*Xd;  i += stride) {
        int j = i >> 8, x = i & 255;
        g_WinT[i] = (j < 64) ? K_w[x*64 + j] : Bm_w[x*32 + (j - 64)];
    }
    for (int i = n; i < Xd; i += stride) g_bias[i] = K_b[i] + Bm_b[i] + A_b[i];
}

// ---------------- drive: d[t][b][x] = y_t·K^T + u_t·Bm^T + (K_b+Bm_b+A_b) ----------------
__global__ __launch_bounds__(256) void drive_kernel(
    const float* __restrict__ y, const float* __restrict__ u)
{
    __shared__ __align__(16) float sIn[64*96];
    int t = blockIdx.x, tid = threadIdx.x;
    for (int m = tid; m < 64*64; m += 256) { int b = m >> 6, c = m & 63; sIn[b*96 + c]      = y[(b*Td + t)*64 + c]; }
    for (int m = tid; m < 64*32; m += 256) { int b = m >> 5, c = m & 31; sIn[b*96 + 64 + c] = u[(b*Td + t)*32 + c]; }
    __syncthreads();
    int tr = tid >> 5, tc = tid & 31;
    u64 acc[8][4];
    ulonglong2 b01 = *(const ulonglong2*)&g_bias[tc*8];
    ulonglong2 b23 = *(const ulonglong2*)&g_bias[tc*8 + 4];
    #pragma unroll
    for (int r = 0; r < 8; r++) { acc[r][0]=b01.x; acc[r][1]=b01.y; acc[r][2]=b23.x; acc[r][3]=b23.y; }
    #pragma unroll 4
    for (int j = 0; j < 96; j++) {
        ulonglong2 w01 = *(const ulonglong2*)&g_WinT[j*Xd + tc*8];
        ulonglong2 w23 = *(const ulonglong2*)&g_WinT[j*Xd + tc*8 + 4];
        #pragma unroll
        for (int r = 0; r < 8; r++) {
            u64 vv = bcast2(sIn[(tr*8 + r)*96 + j]);
            fma2(acc[r][0], vv, w01.x); fma2(acc[r][1], vv, w01.y);
            fma2(acc[r][2], vv, w23.x); fma2(acc[r][3], vv, w23.y);
        }
    }
    float* dp = &g_drive[t*Bd*Xd];
    #pragma unroll
    for (int r = 0; r < 8; r++) {
        int b = tr*8 + r;
        ulonglong2 o0; o0.x = acc[r][0]; o0.y = acc[r][1];
        ulonglong2 o1; o1.x = acc[r][2]; o1.y = acc[r][3];
        *(ulonglong2*)&dp[b*Xd + tc*8]     = o0;
        *(ulonglong2*)&dp[b*Xd + tc*8 + 4] = o1;
    }
}

// ---------------- matsq v2: Q = P·P, 128 CTAs (16x32 output tiles) ----------------
__global__ __launch_bounds__(256) void matsq_kernel(
    const float* __restrict__ P, float* __restrict__ Q)
{
    __shared__ __align__(16) float sL[16*68];
    int i0 = (blockIdx.x >> 3) * 16, k0 = (blockIdx.x & 7) * 32;
    int tid = threadIdx.x, tr = tid >> 4, tc = tid & 15;   // tr: row 0-15, tc: col pair 0-15
    u64 acc = 0ull;
    for (int jb = 0; jb < 4; jb++) {
        for (int m = tid; m < 16*64; m += 256) {
            int r = m >> 6, c = m & 63;
            sL[r*68 + c] = P[(i0 + r)*Xd + jb*64 + c];
        }
        __syncthreads();
        #pragma unroll 8
        for (int j = 0; j < 64; j++) {
            u64 w = *(const u64*)&P[(jb*64 + j)*Xd + k0 + tc*2];
            u64 vv = bcast2(sL[tr*68 + j]);
            fma2(acc, vv, w);
        }
        __syncthreads();
    }
    *(u64*)&Q[(i0 + tr)*Xd + k0 + tc*2] = acc;
}

// ---------------- scan_main v3 (R12 winner): dup-state smem + conflict-free weights ----
// V <- V·M + D_k. statesOut (if set) receives the PRE-update state.
// Lane ℓ owns cols {ℓ*4..+3, 128+ℓ*4..+3}; warp w owns rows [w*4, w*4+4).
// sV2 holds duplicated {v,v} u64 per element: packed broadcast comes from LDS, no MOVs.
// smem: sV2 64KB + sM 2x32KB = 128KB dynamic.
#define SCAN_SMEM ((32*Xd*2 + 2*32*Xd)*4)

__global__ __launch_bounds__(256) void scan_main(
    const float* __restrict__ M, const float* __restrict__ D,
    const float* __restrict__ init, float* __restrict__ statesOut,
    float* __restrict__ finalOut, int nSteps)
{
    extern __shared__ __align__(16) float sm[];
    u64*   sV2 = (u64*)sm;            // 32*256 u64 (dup pairs)
    float* sM  = sm + 32*Xd*2;        // 2 * 32*256 float
    int chunk = blockIdx.x >> 1;
    int b0 = (blockIdx.x & 1) * 32;
    int tid = threadIdx.x, w = tid >> 5, ln = tid & 31;
    int c0 = ln*4, c1 = 128 + ln*4;   // owned col bases

    if (init) {
        const float4* ip = (const float4*)(init + ((size_t)chunk*Bd + b0)*Xd);
        #pragma unroll
        for (int i = 0; i < 8; i++) {
            float4 v = ip[tid + i*256];
            ulonglong2* dst = (ulonglong2*)&sV2[(tid + i*256)*4];
            ulonglong2 a; a.x = bcast2(v.x); a.y = bcast2(v.y);
            ulonglong2 b; b.x = bcast2(v.z); b.y = bcast2(v.w);
            dst[0] = a; dst[1] = b;
        }
    } else {
        ulonglong2 z; z.x = 0ull; z.y = 0ull;
        #pragma unroll
        for (int i = 0; i < 8; i++) {
            ulonglong2* dst = (ulonglong2*)&sV2[(tid + i*256)*4];
            dst[0] = z; dst[1] = z;
        }
    }
    {   // stage M tile 0 into buffer 0
        const float4* src = (const float4*)M;
        float4* dst = (float4*)sM;
        #pragma unroll
        for (int i = 0; i < 8; i++) dst[tid + i*256] = src[tid + i*256];
    }
    __syncthreads();
    int buf = 0;

    for (int k = 0; k < nSteps; k++) {
        size_t rowbase = ((size_t)(chunk*nSteps + k)*Bd + b0)*Xd;
        // acc init from D: packed col pairs are just u64 loads of adjacent floats
        u64 acc[4][4];
        {
            const float* Dp = D + rowbase;
            #pragma unroll
            for (int r = 0; r < 4; r++) {
                ulonglong2 a0 = *(const ulonglong2*)&Dp[(w*4 + r)*Xd + c0];
                ulonglong2 a1 = *(const ulonglong2*)&Dp[(w*4 + r)*Xd + c1];
                acc[r][0]=a0.x; acc[r][1]=a0.y; acc[r][2]=a1.x; acc[r][3]=a1.y;
            }
        }
        if (statesOut) {   // extract lows of dup pairs -> contiguous floats
            float2* sp = (float2*)(statesOut + rowbase);
            #pragma unroll
            for (int i = 0; i < 16; i++) {
                ulonglong2 q = ((const ulonglong2*)sV2)[tid + i*256];
                float2 o; o.x = unpack2(q.x).x; o.y = unpack2(q.y).x;
                sp[tid + i*256] = o;
            }
        }
        for (int tt = 0; tt < 8; tt++) {
            int nt = (tt + 1) & 7;
            float4 pf[8];
            {   // prefetch next M tile (cyclic; feeds next iter/step)
                const float4* src = (const float4*)(M + nt*32*Xd);
                #pragma unroll
                for (int i = 0; i < 8; i++) pf[i] = src[tid + i*256];
            }
            const float* mb = sM + buf*(32*Xd);
            #pragma unroll 2
            for (int jj = 0; jj < 32; jj += 4) {
                ulonglong2 va[4], vb[4];   // dup pairs for j..j+3, 4 rows (LDS broadcast)
                #pragma unroll
                for (int r = 0; r < 4; r++) {
                    const ulonglong2* vp = (const ulonglong2*)&sV2[(w*4 + r)*Xd + tt*32 + jj];
                    va[r] = vp[0]; vb[r] = vp[1];
                }
                #pragma unroll
                for (int q = 0; q < 4; q++) {
                    ulonglong2 mA = *(const ulonglong2*)&mb[(jj+q)*Xd + c0];  // conflict-free
                    ulonglong2 mB = *(const ulonglong2*)&mb[(jj+q)*Xd + c1];
                    #pragma unroll
                    for (int r = 0; r < 4; r++) {
                        u64 vv = (q == 0) ? va[r].x : (q == 1) ? va[r].y
                               : (q == 2) ? vb[r].x : vb[r].y;
                        fma2(acc[r][0], vv, mA.x); fma2(acc[r][1], vv, mA.y);
                        fma2(acc[r][2], vv, mB.x); fma2(acc[r][3], vv, mB.y);
                    }
                }
            }
            {   // stage prefetched tile into the other buffer
                float4* dst = (float4*)(sM + (buf^1)*(32*Xd));
                #pragma unroll
                for (int i = 0; i < 8; i++) dst[tid + i*256] = pf[i];
            }
            __syncthreads();
            buf ^= 1;
        }
        // write new V (duplicated)
        #pragma unroll
        for (int r = 0; r < 4; r++) {
            *(ulonglong2*)&sV2[(w*4 + r)*Xd + c0]     = dup2(acc[r][0]);
            *(ulonglong2*)&sV2[(w*4 + r)*Xd + c0 + 2] = dup2(acc[r][1]);
            *(ulonglong2*)&sV2[(w*4 + r)*Xd + c1]     = dup2(acc[r][2]);
            *(ulonglong2*)&sV2[(w*4 + r)*Xd + c1 + 2] = dup2(acc[r][3]);
        }
        __syncthreads();
    }
    if (finalOut) {
        float2* fp = (float2*)(finalOut + ((size_t)chunk*Bd + b0)*Xd);
        #pragma unroll
        for (int i = 0; i < 16; i++) {
            ulonglong2 q = ((const ulonglong2*)sV2)[tid + i*256];
            float2 o; o.x = unpack2(q.x).x; o.y = unpack2(q.y).x;
            fp[tid + i*256] = o;
        }
    }
}

// ---------------- carry scan v2: 64 CTAs x 1 batch row, 256 threads (1 col each) -------
__global__ __launch_bounds__(256) void scan_carry(
    const float* __restrict__ M, const float* __restrict__ D,
    float* __restrict__ statesOut, int nSteps)
{
    __shared__ __align__(16) float sV[Xd];
    int b0 = blockIdx.x;                 // one batch row per CTA
    int tid = threadIdx.x;               // one column per thread
    if (tid < Xd/4) ((float4*)sV)[tid] = make_float4(0.f,0.f,0.f,0.f);
    __syncthreads();
    for (int k = 0; k < nSteps; k++) {
        size_t rowbase = ((size_t)k*Bd + b0)*Xd;
        if (tid < Xd/4)
            ((float4*)(statesOut + rowbase))[tid] = ((const float4*)sV)[tid];
        float acc = D[rowbase + tid];
        #pragma unroll 8
        for (int j = 0; j < Xd; j++)
            acc = fmaf(sV[j], M[j*Xd + tid], acc);
        __syncthreads();
        sV[tid] = acc;
        __syncthreads();
    }
}

// ---------------- heads v3 (R12 winner): dup-state sX2, conflict-free L1 weights -------
// smem: sX2 64x256 u64 (128KB) + sW 32x256 f (32KB, single buffer) + sH 64x256 f (64KB)
//       = 224KB dynamic (<= 227KB opt-in).
#define HEADS_SMEM ((64*Xd*2 + 32*Xd + 64*Xd)*4)

// sH = relu(X @ W1T + b1); warp w -> rows [w*8,+8), lane cols {ℓ*4, 128+ℓ*4}.
__device__ __forceinline__ void mlp_l1(
    const float* __restrict__ W1, const float* __restrict__ b1,
    const u64* sX2, float* sW, float* sH, int tid)
{
    int w = tid >> 5, ln = tid & 31;
    int c0 = ln*4, c1 = 128 + ln*4;
    u64 acc[8][4];
    {
        ulonglong2 bb0 = *(const ulonglong2*)&b1[c0];
        ulonglong2 bb1 = *(const ulonglong2*)&b1[c1];
        #pragma unroll
        for (int r = 0; r < 8; r++) { acc[r][0]=bb0.x; acc[r][1]=bb0.y; acc[r][2]=bb1.x; acc[r][3]=bb1.y; }
    }
    {   // stage tile 0
        const float4* src = (const float4*)W1;
        float4* dst = (float4*)sW;
        #pragma unroll
        for (int i = 0; i < 8; i++) dst[tid + i*256] = src[tid + i*256];
    }
    __syncthreads();
    for (int kt = 0; kt < 8; kt++) {
        float4 pf[8];
        if (kt < 7) {
            const float4* src = (const float4*)(W1 + (kt+1)*32*Xd);
            #pragma unroll
            for (int i = 0; i < 8; i++) pf[i] = src[tid + i*256];
        }
        #pragma unroll 2
        for (int jj = 0; jj < 32; jj += 4) {
            ulonglong2 va[8], vb[8];
            #pragma unroll
            for (int r = 0; r < 8; r++) {
                const ulonglong2* vp = (const ulonglong2*)&sX2[(w*8 + r)*Xd + kt*32 + jj];
                va[r] = vp[0]; vb[r] = vp[1];
            }
            #pragma unroll
            for (int q = 0; q < 4; q++) {
                ulonglong2 mA = *(const ulonglong2*)&sW[(jj+q)*Xd + c0];
                ulonglong2 mB = *(const ulonglong2*)&sW[(jj+q)*Xd + c1];
                #pragma unroll
                for (int r = 0; r < 8; r++) {
                    u64 vv = (q == 0) ? va[r].x : (q == 1) ? va[r].y
                           : (q == 2) ? vb[r].x : vb[r].y;
                    fma2(acc[r][0], vv, mA.x); fma2(acc[r][1], vv, mA.y);
                    fma2(acc[r][2], vv, mB.x); fma2(acc[r][3], vv, mB.y);
                }
            }
        }
        __syncthreads();                 // all reads of sW done
        if (kt < 7) {
            float4* dst = (float4*)sW;
            #pragma unroll
            for (int i = 0; i < 8; i++) dst[tid + i*256] = pf[i];
            __syncthreads();             // new tile visible
        }
    }
    #pragma unroll
    for (int r = 0; r < 8; r++) {
        float2 p0 = unpack2(acc[r][0]), p1 = unpack2(acc[r][1]);
        float2 p2 = unpack2(acc[r][2]), p3 = unpack2(acc[r][3]);
        float4 o0 = {fmaxf(p0.x,0.f), fmaxf(p0.y,0.f), fmaxf(p1.x,0.f), fmaxf(p1.y,0.f)};
        float4 o1 = {fmaxf(p2.x,0.f), fmaxf(p2.y,0.f), fmaxf(p3.x,0.f), fmaxf(p3.y,0.f)};
        *(float4*)&sH[(w*8 + r)*Xd + c0] = o0;   // contiguous, conflict-free
        *(float4*)&sH[(w*8 + r)*Xd + c1] = o1;
    }
    __syncthreads();
}

__global__ __launch_bounds__(256) void heads_kernel(
    const float* __restrict__ Cy1_b, const float* __restrict__ Cy2_b,
    const float* __restrict__ Cz1_b, const float* __restrict__ Cz2_b,
    float* __restrict__ outY, float* __restrict__ outZ)
{
    extern __shared__ __align__(16) float sm[];
    u64*   sX2 = (u64*)sm;              // 64*256 u64 (dup)
    float* sW  = sm + 64*Xd*2;          // 32*256
    float* sH  = sm + 64*Xd*2 + 32*Xd;  // 64*256
    int t = blockIdx.x, tid = threadIdx.x;

    {   // load X_t and duplicate into sX2
        const float4* xp = (const float4*)&g_Xst[(size_t)t*Bd*Xd];
        #pragma unroll
        for (int i = 0; i < 16; i++) {
            float4 v = xp[tid + i*256];
            ulonglong2* dst = (ulonglong2*)&sX2[(tid + i*256)*4];
            ulonglong2 a; a.x = bcast2(v.x); a.y = bcast2(v.y);
            ulonglong2 b; b.x = bcast2(v.z); b.y = bcast2(v.w);
            dst[0] = a; dst[1] = b;
        }
    }
    __syncthreads();

    // ===== Y head =====
    mlp_l1(g_Cy1T, Cy1_b, sX2, sW, sH, tid);
    {   // L2-Y: 64x64 = sigm(H @ Cy2T + b2); 8 warps x 8 rows, lane -> col pair
        int tr = tid >> 5, lane = tid & 31;
        u64 acc[8];
        u64 bb = *(const u64*)&Cy2_b[lane*2];
        #pragma unroll
        for (int r = 0; r < 8; r++) acc[r] = bb;
        #pragma unroll 4
        for (int jj = 0; jj < Xd; jj += 4) {
            float4 v[8];
            #pragma unroll
            for (int r = 0; r < 8; r++) v[r] = *(const float4*)&sH[(tr*8 + r)*Xd + jj];
            #pragma unroll
            for (int q = 0; q < 4; q++) {
                u64 wv = *(const u64*)&g_Cy2T[(jj+q)*YHd + lane*2];
                #pragma unroll
                for (int r = 0; r < 8; r++) fma2(acc[r], bcast2(fget(v[r], q)), wv);
            }
        }
        #pragma unroll
        for (int r = 0; r < 8; r++) {
            int b = tr*8 + r;
            float2 p = unpack2(acc[r]);
            float2 o = {sigm(p.x), sigm(p.y)};
            *(float2*)&outY[((size_t)b*Td + t)*YHd + lane*2] = o;
        }
    }
    __syncthreads();

    // ===== Z head =====
    mlp_l1(g_Cz1T, Cz1_b, sX2, sW, sH, tid);
    {   // L2-Z: 64x16; 4 threads per row, 4 cols each
        int row = tid >> 2, cz = (tid & 3) * 4;
        ulonglong2 acc = *(const ulonglong2*)&Cz2_b[cz];
        #pragma unroll 4
        for (int jj = 0; jj < Xd; jj += 4) {
            float4 v = *(const float4*)&sH[row*Xd + jj];
            #pragma unroll
            for (int q = 0; q < 4; q++) {
                ulonglong2 wv = *(const ulonglong2*)&g_Cz2T[(jj+q)*ZHd + cz];
                u64 hv = bcast2(fget(v, q));
                fma2(acc.x, hv, wv.x); fma2(acc.y, hv, wv.y);
            }
        }
        float2 p0 = unpack2(acc.x), p1 = unpack2(acc.y);
        float4 o = {sigm(p0.x), sigm(p0.y), sigm(p1.x), sigm(p1.y)};
        *(float4*)&outZ[((size_t)row*Td + t)*ZHd + cz] = o;
    }
}

// ---------------- launch ----------------
extern "C" void kernel_launch(void* const* d_in, const int* in_sizes, int n_in,
                              void* d_out, int out_size)
{
    (void)in_sizes; (void)n_in; (void)out_size;
    const float* y     = (const float*)d_in[0];
    const float* u     = (const float*)d_in[1];
    const float* A_w   = (const float*)d_in[2];
    const float* A_b   = (const float*)d_in[3];
    const float* K_w   = (const float*)d_in[4];
    const float* K_b   = (const float*)d_in[5];
    const float* Bm_w  = (const float*)d_in[6];
    const float* Bm_b  = (const float*)d_in[7];
    const float* Cy1_w = (const float*)d_in[8];
    const float* Cy1_b = (const float*)d_in[9];
    const float* Cy2_w = (const float*)d_in[10];
    const float* Cy2_b = (const float*)d_in[11];
    const float* Cz1_w = (const float*)d_in[12];
    const float* Cz1_b = (const float*)d_in[13];
    const float* Cz2_w = (const float*)d_in[14];
    const float* Cz2_b = (const float*)d_in[15];
    float* outY = (float*)d_out;
    float* outZ = outY + (size_t)Bd*Td*YHd;

    float *pM, *pP0, *pP1, *pDrive, *pE, *pX0, *pX;
    cudaGetSymbolAddress((void**)&pM,  g_M);
    cudaGetSymbolAddress((void**)&pP0, g_P0);
    cudaGetSymbolAddress((void**)&pP1, g_P1);
    cudaGetSymbolAddress((void**)&pDrive, g_drive);
    cudaGetSymbolAddress((void**)&pE,  g_E);
    cudaGetSymbolAddress((void**)&pX0, g_X0);
    cudaGetSymbolAddress((void**)&pX,  g_Xst);

    cudaFuncSetAttribute(scan_main,   cudaFuncAttributeMaxDynamicSharedMemorySize, SCAN_SMEM);
    cudaFuncSetAttribute(heads_kernel, cudaFuncAttributeMaxDynamicSharedMemorySize, HEADS_SMEM);

    setup_kernel<<<256, 256>>>(A_w, A_b, K_w, K_b, Bm_w, Bm_b, Cy1_w, Cz1_w, Cy2_w, Cz2_w);
    drive_kernel<<<Td, 256>>>(y, u);

    // Mc = M^32 by repeated squaring (wide 128-CTA GEMMs)
    matsq_kernel<<<128, 256>>>(pM,  pP0);   // M^2
    matsq_kernel<<<128, 256>>>(pP0, pP1);   // M^4
    matsq_kernel<<<128, 256>>>(pP1, pP0);   // M^8
    matsq_kernel<<<128, 256>>>(pP0, pP1);   // M^16
    matsq_kernel<<<128, 256>>>(pP1, pP0);   // M^32

    // pass 1: per-chunk zero-start recurrences -> chunk end states E_c
    scan_main<<<NCc*2, 256, SCAN_SMEM>>>(pM, pDrive, nullptr, nullptr, pE, Cc);
    // carry: X0_{c+1} = X0_c * M^32 + E_c  (stores pre-update X0_c)
    scan_carry<<<Bd, 256>>>(pP0, pE, pX0, NCc);
    // pass 2: re-run each chunk from true X0_c, streaming pre-update states
    scan_main<<<NCc*2, 256, SCAN_SMEM>>>(pM, pDrive, pX0, pX, nullptr, Cc);

    heads_kernel<<<Td, 256, HEADS_SMEM>>>(Cy1_b, Cy2_b, Cz1_b, Cz2_b, outY, outZ);
}